// round 10
// baseline (speedup 1.0000x reference)
#include <cuda_runtime.h>
#include <math.h>

constexpr int DIM   = 192;
constexpr int SLICE = DIM * DIM;
constexpr int NVOX  = DIM * SLICE;

constexpr int OUT = 28;                      // output span per tile (32 - 2*2 halo)
constexpr int NB  = (DIM + OUT - 1) / OUT;   // 7
constexpr int CHZ = 24, NCH = DIM / CHZ;     // 8 z-chunks
constexpr unsigned FULL = 0xffffffffu;

__device__ float  g_buf[2][4 * NVOX];
__device__ double g_acc[4];  // {sum(skelT*pred), sum(skelT), sum(skelP*target), sum(skelP)}

// MODE 0: raw inputs -> dst ; MODE 1: buf -> buf ; MODE 2: buf -> sums
template <int MODE>
__global__ __launch_bounds__(256, 5)
void fused_iter(int srcSel, int dstSel,
                const float* __restrict__ pred, const float* __restrict__ target) {
    // y-boundary row exchange; float2 = the thread's two adjacent x columns
    __shared__ float2 xex[4][2][16][16];   // [slot][top/bot][ty][tx]
    __shared__ float2 mex[2][2][16][16];   // [parity][top/bot][ty][tx]

    const int tx = threadIdx.x;            // 0..15, owns x = 2tx, 2tx+1 (footprint 32)
    const int ty = threadIdx.y;            // 0..15, owns y = 2ty, 2ty+1 (footprint 32)
    const int chunk = blockIdx.z % NCH;
    const int v     = blockIdx.z / NCH;
    const int zc    = chunk * CHZ;

    const int gx0 = blockIdx.x * OUT + 2 * tx - 2;
    const int gy0 = blockIdx.y * OUT + 2 * ty - 2;
    const bool gxin0 = (unsigned)gx0 < (unsigned)DIM;
    const bool gxin1 = (unsigned)(gx0 + 1) < (unsigned)DIM;
    const bool gyin0 = (unsigned)gy0 < (unsigned)DIM;
    const bool gyin1 = (unsigned)(gy0 + 1) < (unsigned)DIM;
    const int lx0 = 2 * tx, ly0 = 2 * ty;
    const bool colout0 = (lx0 >= 2 && lx0 <= 29) && gxin0;
    const bool colout1 = (lx0 + 1 >= 2 && lx0 + 1 <= 29) && gxin1;
    const bool rowout0 = (ly0 >= 2 && ly0 <= 29) && gyin0;
    const bool rowout1 = (ly0 + 1 >= 2 && ly0 + 1 <= 29) && gyin1;
    const int off00 = gy0 * DIM + gx0;     // single base offset; neighbors derived

    const float* src;
    if (MODE == 0) src = (v < 2) ? target + (size_t)v * NVOX
                                 : pred + (size_t)(v - 2) * NVOX;
    else           src = g_buf[srcSel] + (size_t)v * NVOX;
    float* dst = g_buf[dstSel] + (size_t)v * NVOX;
    const float* other = nullptr;
    if (MODE == 2) other = (v < 2) ? pred + (size_t)v * NVOX
                                   : target + (size_t)(v - 2) * NVOX;

    const float PINF = __int_as_float(0x7f800000);
    const float NINF = -PINF;

    auto loadPlane = [&](int z, float xv[2][2]) {
        bool zin = (unsigned)z < (unsigned)DIM;
        const float* sp = src + (size_t)z * SLICE + off00;
        #pragma unroll
        for (int j = 0; j < 2; ++j) {
            bool gj = (j == 0) ? gyin0 : gyin1;
            const float* rp = sp + j * DIM;
            if (zin && gj) {
                if (gxin0 && gxin1) {
                    float2 t = __ldg((const float2*)rp);
                    xv[j][0] = t.x; xv[j][1] = t.y;
                } else {
                    xv[j][0] = gxin0 ? __ldg(rp)     : PINF;
                    xv[j][1] = gxin1 ? __ldg(rp + 1) : PINF;
                }
            } else {
                xv[j][0] = PINF; xv[j][1] = PINF;
            }
        }
    };

    float xa[2][2], xb[2][2], xc[2][2], xd[2][2];
    float mp_[2][2], ca[2][2], cb[2][2];

    loadPlane(zc - 2, xa);
    loadPlane(zc - 1, xb);
    loadPlane(zc,     xc);
    {
        int s1 = (zc - 1 + 8) & 3, s2 = (zc + 8) & 3;
        xex[s1][0][ty][tx] = make_float2(xb[0][0], xb[0][1]);
        xex[s1][1][ty][tx] = make_float2(xb[1][0], xb[1][1]);
        xex[s2][0][ty][tx] = make_float2(xc[0][0], xc[0][1]);
        xex[s2][1][ty][tx] = make_float2(xc[1][0], xc[1][1]);
    }
    #pragma unroll
    for (int j = 0; j < 2; ++j)
        #pragma unroll
        for (int k = 0; k < 2; ++k) { mp_[j][k] = NINF; ca[j][k] = NINF; cb[j][k] = NINF; }
    __syncthreads();

    float accS = 0.0f, accP = 0.0f;

    #pragma unroll 2
    for (int p = zc - 1; p <= zc + CHZ; ++p) {
        // (a) prefetch plane p+2 (consumed one plane-step later) + publish rows
        loadPlane(p + 2, xd);
        int sw = (p + 2 + 8) & 3;
        xex[sw][0][ty][tx] = make_float2(xd[0][0], xd[0][1]);
        xex[sw][1][ty][tx] = make_float2(xd[1][0], xd[1][1]);

        // (b) 7-pt min -> M(p) from resident xa/xb/xc
        float m[2][2];
        {
            int sp_ = (p + 8) & 3;
            float2 yup = (ty > 0)  ? xex[sp_][1][ty - 1][tx] : make_float2(PINF, PINF);
            float2 ydn = (ty < 15) ? xex[sp_][0][ty + 1][tx] : make_float2(PINF, PINF);
            bool pin = (unsigned)p < (unsigned)DIM;
            #pragma unroll
            for (int j = 0; j < 2; ++j) {
                float vL = __shfl_up_sync(FULL, xb[j][1], 1, 16);
                if (tx == 0)  vL = PINF;
                float vR = __shfl_down_sync(FULL, xb[j][0], 1, 16);
                if (tx == 15) vR = PINF;
                float up0 = (j == 0) ? yup.x : xb[0][0];
                float up1 = (j == 0) ? yup.y : xb[0][1];
                float dn0 = (j == 1) ? ydn.x : xb[1][0];
                float dn1 = (j == 1) ? ydn.y : xb[1][1];
                float t  = fminf(xb[j][0], xb[j][1]);
                float m0 = fminf(fminf(t, vL), fminf(xa[j][0], xc[j][0]));
                m0 = fminf(m0, fminf(up0, dn0));
                float m1 = fminf(fminf(t, vR), fminf(xa[j][1], xc[j][1]));
                m1 = fminf(m1, fminf(up1, dn1));
                bool pj = pin && ((j == 0) ? gyin0 : gyin1);
                m[j][0] = (pj && gxin0) ? m0 : NINF;
                m[j][1] = (pj && gxin1) ? m1 : NINF;
            }
        }
        int par = p & 1;
        mex[par][0][ty][tx] = make_float2(m[0][0], m[0][1]);
        mex[par][1][ty][tx] = make_float2(m[1][0], m[1][1]);
        __syncthreads();   // single barrier per plane

        // (c) V = 3-y-max, C2 = 3-x-max of V
        float cc[2][2];
        {
            float2 mup = (ty > 0)  ? mex[par][1][ty - 1][tx] : make_float2(NINF, NINF);
            float2 mdn = (ty < 15) ? mex[par][0][ty + 1][tx] : make_float2(NINF, NINF);
            float s0 = fmaxf(m[0][0], m[1][0]);
            float s1 = fmaxf(m[0][1], m[1][1]);
            float Vr[2][2];
            Vr[0][0] = fmaxf(mup.x, s0); Vr[0][1] = fmaxf(mup.y, s1);
            Vr[1][0] = fmaxf(s0, mdn.x); Vr[1][1] = fmaxf(s1, mdn.y);
            #pragma unroll
            for (int j = 0; j < 2; ++j) {
                float VL = __shfl_up_sync(FULL, Vr[j][1], 1, 16);
                if (tx == 0)  VL = NINF;
                float VR = __shfl_down_sync(FULL, Vr[j][0], 1, 16);
                if (tx == 15) VR = NINF;
                float u = fmaxf(Vr[j][0], Vr[j][1]);
                cc[j][0] = fmaxf(VL, u);
                cc[j][1] = fmaxf(u, VR);
            }
        }

        // (d) emit plane q = p-1
        int q = p - 1;
        if (q >= zc) {
            float o[2][2];
            #pragma unroll
            for (int j = 0; j < 2; ++j)
                #pragma unroll
                for (int k = 0; k < 2; ++k) {
                    float A   = fmaxf(fmaxf(ca[j][k], cb[j][k]), cc[j][k]);
                    float ctr = fmaxf(A - mp_[j][k], 0.0f);
                    o[j][k]   = fmaxf(xa[j][k] - ctr, 0.0f);
                }
            size_t base = (size_t)q * SLICE + off00;
            if (MODE < 2) {
                #pragma unroll
                for (int j = 0; j < 2; ++j) {
                    bool rj = (j == 0) ? rowout0 : rowout1;
                    if (rj) {
                        if (colout0 && colout1) {
                            *(float2*)(dst + base + j * DIM) = make_float2(o[j][0], o[j][1]);
                        } else {
                            if (colout0) dst[base + j * DIM]     = o[j][0];
                            if (colout1) dst[base + j * DIM + 1] = o[j][1];
                        }
                    }
                }
            } else {
                #pragma unroll
                for (int j = 0; j < 2; ++j) {
                    bool rj = (j == 0) ? rowout0 : rowout1;
                    #pragma unroll
                    for (int k = 0; k < 2; ++k) {
                        bool ck = (k == 0) ? colout0 : colout1;
                        if (rj && ck) {
                            float f = o[j][k];
                            accS += f;
                            accP += f * __ldg(other + base + j * DIM + k);
                        }
                    }
                }
            }
        }

        // (e) rotate register planes
        #pragma unroll
        for (int j = 0; j < 2; ++j)
            #pragma unroll
            for (int k = 0; k < 2; ++k) {
                xa[j][k] = xb[j][k]; xb[j][k] = xc[j][k]; xc[j][k] = xd[j][k];
                ca[j][k] = cb[j][k]; cb[j][k] = cc[j][k];
                mp_[j][k] = m[j][k];
            }
    }

    if (MODE == 2) {
        #pragma unroll
        for (int offm = 16; offm > 0; offm >>= 1) {
            accS += __shfl_down_sync(FULL, accS, offm);
            accP += __shfl_down_sync(FULL, accP, offm);
        }
        int lane = (tx + ty * 16) & 31;
        if (lane == 0) {
            if (v < 2) { atomicAdd(&g_acc[0], (double)accP); atomicAdd(&g_acc[1], (double)accS); }
            else       { atomicAdd(&g_acc[2], (double)accP); atomicAdd(&g_acc[3], (double)accS); }
        }
    }
}

__global__ void zero_acc_kernel() {
    if (threadIdx.x < 4) g_acc[threadIdx.x] = 0.0;
}

__global__ void final_kernel(float* __restrict__ out) {
    double clrecall = (g_acc[0] + 1e-12) / (g_acc[1] + 1e-12);
    double clacc    = (g_acc[2] + 1e-12) / (g_acc[3] + 1e-12);
    double cldice   = 2.0 * clrecall * clacc / (clrecall + clacc);
    out[0] = (float)(1.0 - cldice);
}

extern "C" void kernel_launch(void* const* d_in, const int* in_sizes, int n_in,
                              void* d_out, int out_size) {
    const float* pred   = (const float*)d_in[0];
    const float* target = (const float*)d_in[1];
    float* out = (float*)d_out;

    dim3 blk(16, 16, 1);
    dim3 grd(NB, NB, 4 * NCH);

    zero_acc_kernel<<<1, 32>>>();
    fused_iter<0><<<grd, blk>>>(0, 0, pred, target);   // inputs -> buf0
    fused_iter<1><<<grd, blk>>>(0, 1, pred, target);   // buf0 -> buf1
    fused_iter<1><<<grd, blk>>>(1, 0, pred, target);   // buf1 -> buf0
    fused_iter<1><<<grd, blk>>>(0, 1, pred, target);   // buf0 -> buf1
    fused_iter<2><<<grd, blk>>>(1, 0, pred, target);   // buf1 -> sums
    final_kernel<<<1, 1>>>(out);
}

// round 11
// speedup vs baseline: 1.2490x; 1.2490x over previous
#include <cuda_runtime.h>
#include <math.h>

constexpr int DIM   = 192;
constexpr int SLICE = DIM * DIM;
constexpr int NVOX  = DIM * SLICE;

constexpr int OUT = 28;                      // output span per tile (32 - 2*2 halo)
constexpr int NB  = (DIM + OUT - 1) / OUT;   // 7
constexpr int CHZ = 24, NCH = DIM / CHZ;     // 8 z-chunks
constexpr unsigned FULL = 0xffffffffu;

__device__ float  g_buf[2][4 * NVOX];
__device__ double g_acc[4];  // {sum(skelT*pred), sum(skelT), sum(skelP*target), sum(skelP)}

// MODE 0: raw inputs -> dst ; MODE 1: buf -> buf ; MODE 2: buf -> sums
// INT: block's 32x32 xy-footprint fully inside the volume (no gx/gy checks).
template <int MODE, bool INT>
__device__ __forceinline__ void body(
    const float* __restrict__ src, float* __restrict__ dst,
    const float* __restrict__ other, int v, int zc,
    float2 (*xex)[2][16][16], float2 (*mex)[2][16][16])
{
    const int tx = threadIdx.x;            // 0..15, owns x = 2tx, 2tx+1
    const int ty = threadIdx.y;            // 0..15, owns y = 2ty, 2ty+1
    const int gx0 = blockIdx.x * OUT + 2 * tx - 2;
    const int gy0 = blockIdx.y * OUT + 2 * ty - 2;
    const float PINF = __int_as_float(0x7f800000);
    const float NINF = -PINF;

    bool gxin0 = true, gxin1 = true, gyin0 = true, gyin1 = true;
    if (!INT) {
        gxin0 = (unsigned)gx0 < (unsigned)DIM;
        gxin1 = (unsigned)(gx0 + 1) < (unsigned)DIM;
        gyin0 = (unsigned)gy0 < (unsigned)DIM;
        gyin1 = (unsigned)(gy0 + 1) < (unsigned)DIM;
    }
    const bool ce = (tx >= 1 && tx <= 14);   // local emit columns (both of the pair)
    const bool re = (ty >= 1 && ty <= 14);   // local emit rows (both of the pair)
    const bool colout0 = ce && gxin0, colout1 = ce && gxin1;
    const bool rowout0 = re && gyin0, rowout1 = re && gyin1;

    const int off00 = gy0 * DIM + gx0;

    // rolling cursors (advance by SLICE per plane; deref only when z in range)
    const float* ldc = src + (ptrdiff_t)(zc + 1) * SLICE + off00;  // plane p+2 at first iter
    float*       stc = dst + (ptrdiff_t)(zc - 2) * SLICE + off00;  // plane q (valid once q>=zc)
    const float* otc = (MODE == 2) ? other + (ptrdiff_t)(zc - 2) * SLICE + off00 : nullptr;

    auto loadP = [&](const float* sp, bool zin, float xv[2][2]) {
        if (INT) {
            if (zin) {
                float2 t0 = __ldg((const float2*)sp);
                float2 t1 = __ldg((const float2*)(sp + DIM));
                xv[0][0] = t0.x; xv[0][1] = t0.y;
                xv[1][0] = t1.x; xv[1][1] = t1.y;
            } else {
                xv[0][0] = xv[0][1] = xv[1][0] = xv[1][1] = PINF;
            }
        } else {
            #pragma unroll
            for (int j = 0; j < 2; ++j) {
                bool gj = (j == 0) ? gyin0 : gyin1;
                const float* rp = sp + j * DIM;
                if (zin && gj) {
                    if (gxin0 && gxin1) {
                        float2 t = __ldg((const float2*)rp);
                        xv[j][0] = t.x; xv[j][1] = t.y;
                    } else {
                        xv[j][0] = gxin0 ? __ldg(rp)     : PINF;
                        xv[j][1] = gxin1 ? __ldg(rp + 1) : PINF;
                    }
                } else {
                    xv[j][0] = PINF; xv[j][1] = PINF;
                }
            }
        }
    };

    float xa[2][2], xb[2][2], xc[2][2], xd[2][2];
    float mp_[2][2], ca[2][2], cb[2][2];

    loadP(src + (ptrdiff_t)(zc - 2) * SLICE + off00, (unsigned)(zc - 2) < (unsigned)DIM, xa);
    loadP(src + (ptrdiff_t)(zc - 1) * SLICE + off00, (unsigned)(zc - 1) < (unsigned)DIM, xb);
    loadP(src + (ptrdiff_t)zc * SLICE + off00,       true,                               xc);
    {
        int s1 = (zc - 1 + 8) & 3, s2 = (zc + 8) & 3;
        xex[s1][0][ty][tx] = make_float2(xb[0][0], xb[0][1]);
        xex[s1][1][ty][tx] = make_float2(xb[1][0], xb[1][1]);
        xex[s2][0][ty][tx] = make_float2(xc[0][0], xc[0][1]);
        xex[s2][1][ty][tx] = make_float2(xc[1][0], xc[1][1]);
    }
    #pragma unroll
    for (int j = 0; j < 2; ++j)
        #pragma unroll
        for (int k = 0; k < 2; ++k) { mp_[j][k] = NINF; ca[j][k] = NINF; cb[j][k] = NINF; }
    __syncthreads();

    float accS = 0.0f, accP = 0.0f;

    #pragma unroll 2
    for (int p = zc - 1; p <= zc + CHZ; ++p) {
        // (a) prefetch plane p+2 (consumed one plane-step later) + publish rows
        loadP(ldc, p + 2 < DIM, xd);
        int sw = (p + 2 + 8) & 3;
        xex[sw][0][ty][tx] = make_float2(xd[0][0], xd[0][1]);
        xex[sw][1][ty][tx] = make_float2(xd[1][0], xd[1][1]);

        // (b) 7-pt min -> M(p) from resident xa/xb/xc
        float m[2][2];
        if (p >= 0 && p < DIM) {             // uniform z-validity branch
            int sp_ = (p + 8) & 3;
            float2 yup = (ty > 0)  ? xex[sp_][1][ty - 1][tx] : make_float2(PINF, PINF);
            float2 ydn = (ty < 15) ? xex[sp_][0][ty + 1][tx] : make_float2(PINF, PINF);
            #pragma unroll
            for (int j = 0; j < 2; ++j) {
                float vL = __shfl_up_sync(FULL, xb[j][1], 1, 16);
                if (tx == 0)  vL = PINF;
                float vR = __shfl_down_sync(FULL, xb[j][0], 1, 16);
                if (tx == 15) vR = PINF;
                float up0 = (j == 0) ? yup.x : xb[0][0];
                float up1 = (j == 0) ? yup.y : xb[0][1];
                float dn0 = (j == 1) ? ydn.x : xb[1][0];
                float dn1 = (j == 1) ? ydn.y : xb[1][1];
                float t  = fminf(xb[j][0], xb[j][1]);
                float m0 = fminf(fminf(t, vL), fminf(xa[j][0], xc[j][0]));
                m0 = fminf(m0, fminf(up0, dn0));
                float m1 = fminf(fminf(t, vR), fminf(xa[j][1], xc[j][1]));
                m1 = fminf(m1, fminf(up1, dn1));
                if (INT) {
                    m[j][0] = m0; m[j][1] = m1;
                } else {
                    bool gj = (j == 0) ? gyin0 : gyin1;
                    m[j][0] = (gj && gxin0) ? m0 : NINF;
                    m[j][1] = (gj && gxin1) ? m1 : NINF;
                }
            }
        } else {
            #pragma unroll
            for (int j = 0; j < 2; ++j) { m[j][0] = NINF; m[j][1] = NINF; }
        }
        int par = p & 1;
        mex[par][0][ty][tx] = make_float2(m[0][0], m[0][1]);
        mex[par][1][ty][tx] = make_float2(m[1][0], m[1][1]);
        __syncthreads();   // single barrier per plane

        // (c) V = 3-y-max, C2 = 3-x-max of V
        float cc[2][2];
        {
            float2 mup = (ty > 0)  ? mex[par][1][ty - 1][tx] : make_float2(NINF, NINF);
            float2 mdn = (ty < 15) ? mex[par][0][ty + 1][tx] : make_float2(NINF, NINF);
            float s0 = fmaxf(m[0][0], m[1][0]);
            float s1 = fmaxf(m[0][1], m[1][1]);
            float Vr[2][2];
            Vr[0][0] = fmaxf(mup.x, s0); Vr[0][1] = fmaxf(mup.y, s1);
            Vr[1][0] = fmaxf(s0, mdn.x); Vr[1][1] = fmaxf(s1, mdn.y);
            #pragma unroll
            for (int j = 0; j < 2; ++j) {
                float VL = __shfl_up_sync(FULL, Vr[j][1], 1, 16);
                if (tx == 0)  VL = NINF;
                float VR = __shfl_down_sync(FULL, Vr[j][0], 1, 16);
                if (tx == 15) VR = NINF;
                float u = fmaxf(Vr[j][0], Vr[j][1]);
                cc[j][0] = fmaxf(VL, u);
                cc[j][1] = fmaxf(u, VR);
            }
        }

        // (d) emit plane q = p-1
        int q = p - 1;
        if (q >= zc) {
            float o[2][2];
            #pragma unroll
            for (int j = 0; j < 2; ++j)
                #pragma unroll
                for (int k = 0; k < 2; ++k) {
                    float A   = fmaxf(fmaxf(ca[j][k], cb[j][k]), cc[j][k]);
                    float ctr = fmaxf(A - mp_[j][k], 0.0f);
                    o[j][k]   = fmaxf(xa[j][k] - ctr, 0.0f);
                }
            if (INT) {
                if (MODE < 2) {
                    if (ce && re) {
                        *(float2*)stc         = make_float2(o[0][0], o[0][1]);
                        *(float2*)(stc + DIM) = make_float2(o[1][0], o[1][1]);
                    }
                } else {
                    if (ce && re) {
                        accS += (o[0][0] + o[0][1]) + (o[1][0] + o[1][1]);
                        accP += o[0][0] * __ldg(otc)
                              + o[0][1] * __ldg(otc + 1)
                              + o[1][0] * __ldg(otc + DIM)
                              + o[1][1] * __ldg(otc + DIM + 1);
                    }
                }
            } else {
                if (MODE < 2) {
                    #pragma unroll
                    for (int j = 0; j < 2; ++j) {
                        bool rj = (j == 0) ? rowout0 : rowout1;
                        if (rj) {
                            if (colout0 && colout1) {
                                *(float2*)(stc + j * DIM) = make_float2(o[j][0], o[j][1]);
                            } else {
                                if (colout0) stc[j * DIM]     = o[j][0];
                                if (colout1) stc[j * DIM + 1] = o[j][1];
                            }
                        }
                    }
                } else {
                    #pragma unroll
                    for (int j = 0; j < 2; ++j) {
                        bool rj = (j == 0) ? rowout0 : rowout1;
                        #pragma unroll
                        for (int k = 0; k < 2; ++k) {
                            bool ck = (k == 0) ? colout0 : colout1;
                            if (rj && ck) {
                                float f = o[j][k];
                                accS += f;
                                accP += f * __ldg(otc + j * DIM + k);
                            }
                        }
                    }
                }
            }
        }

        // (e) advance cursors + rotate register planes
        ldc += SLICE;
        stc += SLICE;
        if (MODE == 2) otc += SLICE;
        #pragma unroll
        for (int j = 0; j < 2; ++j)
            #pragma unroll
            for (int k = 0; k < 2; ++k) {
                xa[j][k] = xb[j][k]; xb[j][k] = xc[j][k]; xc[j][k] = xd[j][k];
                ca[j][k] = cb[j][k]; cb[j][k] = cc[j][k];
                mp_[j][k] = m[j][k];
            }
    }

    if (MODE == 2) {
        #pragma unroll
        for (int offm = 16; offm > 0; offm >>= 1) {
            accS += __shfl_down_sync(FULL, accS, offm);
            accP += __shfl_down_sync(FULL, accP, offm);
        }
        int lane = (tx + ty * 16) & 31;
        if (lane == 0) {
            if (v < 2) { atomicAdd(&g_acc[0], (double)accP); atomicAdd(&g_acc[1], (double)accS); }
            else       { atomicAdd(&g_acc[2], (double)accP); atomicAdd(&g_acc[3], (double)accS); }
        }
    }
}

template <int MODE>
__global__ __launch_bounds__(256)
void fused_iter(int srcSel, int dstSel,
                const float* __restrict__ pred, const float* __restrict__ target) {
    __shared__ float2 xex[4][2][16][16];   // [slot][top/bot][ty][tx]
    __shared__ float2 mex[2][2][16][16];   // [parity][top/bot][ty][tx]

    const int v  = blockIdx.z / NCH;
    const int zc = (blockIdx.z % NCH) * CHZ;

    const float* src;
    if (MODE == 0) src = (v < 2) ? target + (size_t)v * NVOX
                                 : pred + (size_t)(v - 2) * NVOX;
    else           src = g_buf[srcSel] + (size_t)v * NVOX;
    float* dst = g_buf[dstSel] + (size_t)v * NVOX;
    const float* other = nullptr;
    if (MODE == 2) other = (v < 2) ? pred + (size_t)v * NVOX
                                   : target + (size_t)(v - 2) * NVOX;

    const bool interior = (blockIdx.x >= 1 && blockIdx.x <= 5 &&
                           blockIdx.y >= 1 && blockIdx.y <= 5);
    if (interior) body<MODE, true >(src, dst, other, v, zc, xex, mex);
    else          body<MODE, false>(src, dst, other, v, zc, xex, mex);
}

__global__ void zero_acc_kernel() {
    if (threadIdx.x < 4) g_acc[threadIdx.x] = 0.0;
}

__global__ void final_kernel(float* __restrict__ out) {
    double clrecall = (g_acc[0] + 1e-12) / (g_acc[1] + 1e-12);
    double clacc    = (g_acc[2] + 1e-12) / (g_acc[3] + 1e-12);
    double cldice   = 2.0 * clrecall * clacc / (clrecall + clacc);
    out[0] = (float)(1.0 - cldice);
}

extern "C" void kernel_launch(void* const* d_in, const int* in_sizes, int n_in,
                              void* d_out, int out_size) {
    const float* pred   = (const float*)d_in[0];
    const float* target = (const float*)d_in[1];
    float* out = (float*)d_out;

    dim3 blk(16, 16, 1);
    dim3 grd(NB, NB, 4 * NCH);

    zero_acc_kernel<<<1, 32>>>();
    fused_iter<0><<<grd, blk>>>(0, 0, pred, target);   // inputs -> buf0
    fused_iter<1><<<grd, blk>>>(0, 1, pred, target);   // buf0 -> buf1
    fused_iter<1><<<grd, blk>>>(1, 0, pred, target);   // buf1 -> buf0
    fused_iter<1><<<grd, blk>>>(0, 1, pred, target);   // buf0 -> buf1
    fused_iter<2><<<grd, blk>>>(1, 0, pred, target);   // buf1 -> sums
    final_kernel<<<1, 1>>>(out);
}

// round 12
// speedup vs baseline: 1.3933x; 1.1155x over previous
#include <cuda_runtime.h>
#include <math.h>

constexpr int DIM   = 192;
constexpr int SLICE = DIM * DIM;
constexpr int NVOX  = DIM * SLICE;

constexpr int OUT = 28;                      // output span per tile (32 - 2*2 halo)
constexpr int NB  = 7;
constexpr int CHZ = 16, NCH = DIM / CHZ;     // 12 z-chunks -> grid z = 48
constexpr unsigned FULL = 0xffffffffu;

__device__ float  g_buf[2][4 * NVOX];
__device__ double g_acc[4];  // {sum(skelT*pred), sum(skelT), sum(skelP*target), sum(skelP)}

// MODE 0: raw inputs -> dst ; MODE 1: buf -> buf ; MODE 2: buf -> sums
// INT: block's 32x32 xy-footprint fully inside the volume.
template <int MODE, bool INT>
__device__ __forceinline__ void body(
    const float* __restrict__ src, float* __restrict__ dst,
    const float* __restrict__ other, int v, int zc,
    float2 (*xex)[2][16][16], float2 (*mex)[2][16][16])
{
    const int tx = threadIdx.x;            // 0..15, owns x = 2tx, 2tx+1
    const int ty = threadIdx.y;            // 0..15, owns y = 2ty, 2ty+1
    const int gx0 = blockIdx.x * OUT + 2 * tx - 2;
    const int gy0 = blockIdx.y * OUT + 2 * ty - 2;
    const float PINF = __int_as_float(0x7f800000);
    const float NINF = -PINF;

    bool gxin0 = true, gxin1 = true, gyin0 = true, gyin1 = true;
    if (!INT) {
        gxin0 = (unsigned)gx0 < (unsigned)DIM;
        gxin1 = (unsigned)(gx0 + 1) < (unsigned)DIM;
        gyin0 = (unsigned)gy0 < (unsigned)DIM;
        gyin1 = (unsigned)(gy0 + 1) < (unsigned)DIM;
    }
    const bool ce = (tx >= 1 && tx <= 14);
    const bool re = (ty >= 1 && ty <= 14);
    const bool colout0 = ce && gxin0, colout1 = ce && gxin1;
    const bool rowout0 = re && gyin0, rowout1 = re && gyin1;

    const int off00 = gy0 * DIM + gx0;

    auto loadP = [&](const float* sp, bool zin, float xv[2][2]) {
        if (INT) {
            if (zin) {
                float2 t0 = __ldg((const float2*)sp);
                float2 t1 = __ldg((const float2*)(sp + DIM));
                xv[0][0] = t0.x; xv[0][1] = t0.y;
                xv[1][0] = t1.x; xv[1][1] = t1.y;
            } else {
                xv[0][0] = xv[0][1] = xv[1][0] = xv[1][1] = PINF;
            }
        } else {
            #pragma unroll
            for (int j = 0; j < 2; ++j) {
                bool gj = (j == 0) ? gyin0 : gyin1;
                const float* rp = sp + j * DIM;
                if (zin && gj) {
                    if (gxin0 && gxin1) {
                        float2 t = __ldg((const float2*)rp);
                        xv[j][0] = t.x; xv[j][1] = t.y;
                    } else {
                        xv[j][0] = gxin0 ? __ldg(rp)     : PINF;
                        xv[j][1] = gxin1 ? __ldg(rp + 1) : PINF;
                    }
                } else {
                    xv[j][0] = PINF; xv[j][1] = PINF;
                }
            }
        }
    };
    auto pubX = [&](int s, const float xv[2][2]) {
        xex[s][0][ty][tx] = make_float2(xv[0][0], xv[0][1]);
        xex[s][1][ty][tx] = make_float2(xv[1][0], xv[1][1]);
    };
    auto pubM = [&](int s, const float mv[2][2]) {
        mex[s][0][ty][tx] = make_float2(mv[0][0], mv[0][1]);
        mex[s][1][ty][tx] = make_float2(mv[1][0], mv[1][1]);
    };
    // 7-pt min of plane z (xm = x(z-1), xq = x(z), xp = x(z+1)); y-halo via xex[slot]
    auto min7 = [&](const float xm[2][2], const float xq[2][2], const float xp[2][2],
                    int slot, bool pin, float mo[2][2]) {
        if (pin) {
            float2 yup = (ty > 0)  ? xex[slot][1][ty - 1][tx] : make_float2(PINF, PINF);
            float2 ydn = (ty < 15) ? xex[slot][0][ty + 1][tx] : make_float2(PINF, PINF);
            #pragma unroll
            for (int j = 0; j < 2; ++j) {
                float vL = __shfl_up_sync(FULL, xq[j][1], 1, 16);
                if (tx == 0)  vL = PINF;
                float vR = __shfl_down_sync(FULL, xq[j][0], 1, 16);
                if (tx == 15) vR = PINF;
                float up0 = (j == 0) ? yup.x : xq[0][0];
                float up1 = (j == 0) ? yup.y : xq[0][1];
                float dn0 = (j == 1) ? ydn.x : xq[1][0];
                float dn1 = (j == 1) ? ydn.y : xq[1][1];
                float t  = fminf(xq[j][0], xq[j][1]);
                float a0 = fminf(fminf(t, vL), fminf(xm[j][0], xp[j][0]));
                a0 = fminf(a0, fminf(up0, dn0));
                float a1 = fminf(fminf(t, vR), fminf(xm[j][1], xp[j][1]));
                a1 = fminf(a1, fminf(up1, dn1));
                if (INT) {
                    mo[j][0] = a0; mo[j][1] = a1;
                } else {
                    bool gj = (j == 0) ? gyin0 : gyin1;
                    mo[j][0] = (gj && gxin0) ? a0 : NINF;
                    mo[j][1] = (gj && gxin1) ? a1 : NINF;
                }
            }
        } else {
            mo[0][0] = mo[0][1] = mo[1][0] = mo[1][1] = NINF;
        }
    };
    // 3x3 in-plane max of M; y-halo via mex[slot]
    auto maxC2 = [&](const float mv[2][2], int slot, float co[2][2]) {
        float2 mup = (ty > 0)  ? mex[slot][1][ty - 1][tx] : make_float2(NINF, NINF);
        float2 mdn = (ty < 15) ? mex[slot][0][ty + 1][tx] : make_float2(NINF, NINF);
        float s0 = fmaxf(mv[0][0], mv[1][0]);
        float s1 = fmaxf(mv[0][1], mv[1][1]);
        float Vr[2][2];
        Vr[0][0] = fmaxf(mup.x, s0); Vr[0][1] = fmaxf(mup.y, s1);
        Vr[1][0] = fmaxf(s0, mdn.x); Vr[1][1] = fmaxf(s1, mdn.y);
        #pragma unroll
        for (int j = 0; j < 2; ++j) {
            float VL = __shfl_up_sync(FULL, Vr[j][1], 1, 16);
            if (tx == 0)  VL = NINF;
            float VR = __shfl_down_sync(FULL, Vr[j][0], 1, 16);
            if (tx == 15) VR = NINF;
            float u = fmaxf(Vr[j][0], Vr[j][1]);
            co[j][0] = fmaxf(VL, u);
            co[j][1] = fmaxf(u, VR);
        }
    };

    float xA[2][2], xB[2][2], xC[2][2], xD[2][2], xE[2][2];
    float m0[2][2], m1[2][2], mP[2][2], ca[2][2], cb[2][2];

    // ---- prologue: x(zc-2..zc+1) resident; cb = C2(zc-1); mP = M(zc-1) ----
    {
        float xz2[2][2];
        const float* bp = src + off00;
        loadP(bp + (ptrdiff_t)(zc - 2) * SLICE, (unsigned)(zc - 2) < (unsigned)DIM, xz2);
        loadP(bp + (ptrdiff_t)(zc - 1) * SLICE, (unsigned)(zc - 1) < (unsigned)DIM, xA);
        loadP(bp + (ptrdiff_t)zc * SLICE,       true,                               xB);
        loadP(bp + (ptrdiff_t)(zc + 1) * SLICE, true,                               xC);
        pubX((zc - 2) & 3, xz2); pubX((zc - 1) & 3, xA);
        pubX(zc & 3, xB);        pubX((zc + 1) & 3, xC);
        __syncthreads();
        min7(xz2, xA, xB, (zc - 1) & 3, (unsigned)(zc - 1) < (unsigned)DIM, mP);
        pubM((zc - 1) & 3, mP);
        __syncthreads();
        maxC2(mP, (zc - 1) & 3, cb);
        #pragma unroll
        for (int j = 0; j < 2; ++j) { ca[j][0] = NINF; ca[j][1] = NINF; }
    }

    const float* ldc = src + off00 + (ptrdiff_t)(zc + 2) * SLICE;
    float*       stc = dst + off00 + (ptrdiff_t)(zc - 1) * SLICE;
    const float* otc = (MODE == 2) ? other + off00 + (ptrdiff_t)(zc - 1) * SLICE : nullptr;

    float accS = 0.0f, accP = 0.0f;

    // ---- main sweep: two planes (p, p+1) per iteration, one barrier ----
    for (int p = zc; p <= zc + CHZ; p += 2) {
        bool nextIter = (p + 2 <= zc + CHZ);
        loadP(ldc,         p + 2 < DIM,                xD);
        loadP(ldc + SLICE, (p + 3 < DIM) && nextIter,  xE);
        pubX((p + 2) & 3, xD);
        pubX((p + 3) & 3, xE);

        min7(xA, xB, xC, p & 3,       p < DIM,     m0);   // M(p)
        min7(xB, xC, xD, (p + 1) & 3, p + 1 < DIM, m1);   // M(p+1)
        pubM(p & 3, m0);
        pubM((p + 1) & 3, m1);
        __syncthreads();                                  // one barrier / 2 planes

        float cc0[2][2], cc1[2][2];
        maxC2(m0, p & 3, cc0);          // C2(p)
        maxC2(m1, (p + 1) & 3, cc1);    // C2(p+1)

        // emit q1 = p-1 : A=max(ca,cb,cc0), M=mP, x=xA
        if (p > zc) {
            float o[2][2];
            #pragma unroll
            for (int j = 0; j < 2; ++j)
                #pragma unroll
                for (int k = 0; k < 2; ++k) {
                    float A   = fmaxf(fmaxf(ca[j][k], cb[j][k]), cc0[j][k]);
                    float ctr = fmaxf(A - mP[j][k], 0.0f);
                    o[j][k]   = fmaxf(xA[j][k] - ctr, 0.0f);
                }
            if (INT) {
                if (MODE < 2) {
                    if (ce && re) {
                        *(float2*)stc         = make_float2(o[0][0], o[0][1]);
                        *(float2*)(stc + DIM) = make_float2(o[1][0], o[1][1]);
                    }
                } else if (ce && re) {
                    accS += (o[0][0] + o[0][1]) + (o[1][0] + o[1][1]);
                    accP += o[0][0] * __ldg(otc)       + o[0][1] * __ldg(otc + 1)
                          + o[1][0] * __ldg(otc + DIM) + o[1][1] * __ldg(otc + DIM + 1);
                }
            } else {
                #pragma unroll
                for (int j = 0; j < 2; ++j) {
                    bool rj = (j == 0) ? rowout0 : rowout1;
                    #pragma unroll
                    for (int k = 0; k < 2; ++k) {
                        bool ck = (k == 0) ? colout0 : colout1;
                        if (rj && ck) {
                            if (MODE < 2) stc[j * DIM + k] = o[j][k];
                            else {
                                float f = o[j][k];
                                accS += f;
                                accP += f * __ldg(otc + j * DIM + k);
                            }
                        }
                    }
                }
            }
        }
        // emit q2 = p : A=max(cb,cc0,cc1), M=m0, x=xB
        if (p < zc + CHZ) {
            float o[2][2];
            #pragma unroll
            for (int j = 0; j < 2; ++j)
                #pragma unroll
                for (int k = 0; k < 2; ++k) {
                    float A   = fmaxf(fmaxf(cb[j][k], cc0[j][k]), cc1[j][k]);
                    float ctr = fmaxf(A - m0[j][k], 0.0f);
                    o[j][k]   = fmaxf(xB[j][k] - ctr, 0.0f);
                }
            if (INT) {
                if (MODE < 2) {
                    if (ce && re) {
                        *(float2*)(stc + SLICE)       = make_float2(o[0][0], o[0][1]);
                        *(float2*)(stc + SLICE + DIM) = make_float2(o[1][0], o[1][1]);
                    }
                } else if (ce && re) {
                    accS += (o[0][0] + o[0][1]) + (o[1][0] + o[1][1]);
                    accP += o[0][0] * __ldg(otc + SLICE)       + o[0][1] * __ldg(otc + SLICE + 1)
                          + o[1][0] * __ldg(otc + SLICE + DIM) + o[1][1] * __ldg(otc + SLICE + DIM + 1);
                }
            } else {
                #pragma unroll
                for (int j = 0; j < 2; ++j) {
                    bool rj = (j == 0) ? rowout0 : rowout1;
                    #pragma unroll
                    for (int k = 0; k < 2; ++k) {
                        bool ck = (k == 0) ? colout0 : colout1;
                        if (rj && ck) {
                            if (MODE < 2) stc[SLICE + j * DIM + k] = o[j][k];
                            else {
                                float f = o[j][k];
                                accS += f;
                                accP += f * __ldg(otc + SLICE + j * DIM + k);
                            }
                        }
                    }
                }
            }
        }

        // rotate (shift by two planes)
        #pragma unroll
        for (int j = 0; j < 2; ++j)
            #pragma unroll
            for (int k = 0; k < 2; ++k) {
                xA[j][k] = xC[j][k]; xB[j][k] = xD[j][k]; xC[j][k] = xE[j][k];
                ca[j][k] = cc0[j][k]; cb[j][k] = cc1[j][k];
                mP[j][k] = m1[j][k];
            }
        ldc += 2 * SLICE;
        stc += 2 * SLICE;
        if (MODE == 2) otc += 2 * SLICE;
    }

    if (MODE == 2) {
        #pragma unroll
        for (int offm = 16; offm > 0; offm >>= 1) {
            accS += __shfl_down_sync(FULL, accS, offm);
            accP += __shfl_down_sync(FULL, accP, offm);
        }
        int lane = (tx + ty * 16) & 31;
        if (lane == 0) {
            if (v < 2) { atomicAdd(&g_acc[0], (double)accP); atomicAdd(&g_acc[1], (double)accS); }
            else       { atomicAdd(&g_acc[2], (double)accP); atomicAdd(&g_acc[3], (double)accS); }
        }
    }
}

template <int MODE>
__global__ __launch_bounds__(256)
void fused_iter(int srcSel, int dstSel,
                const float* __restrict__ pred, const float* __restrict__ target) {
    __shared__ float2 xex[4][2][16][16];   // [slot][top/bot][ty][tx]
    __shared__ float2 mex[4][2][16][16];   // [slot][top/bot][ty][tx]

    const int v  = blockIdx.z / NCH;
    const int zc = (blockIdx.z % NCH) * CHZ;

    const float* src;
    if (MODE == 0) src = (v < 2) ? target + (size_t)v * NVOX
                                 : pred + (size_t)(v - 2) * NVOX;
    else           src = g_buf[srcSel] + (size_t)v * NVOX;
    float* dst = g_buf[dstSel] + (size_t)v * NVOX;
    const float* other = nullptr;
    if (MODE == 2) other = (v < 2) ? pred + (size_t)v * NVOX
                                   : target + (size_t)(v - 2) * NVOX;

    const bool interior = (blockIdx.x >= 1 && blockIdx.x <= 5 &&
                           blockIdx.y >= 1 && blockIdx.y <= 5);
    if (interior) body<MODE, true >(src, dst, other, v, zc, xex, mex);
    else          body<MODE, false>(src, dst, other, v, zc, xex, mex);
}

__global__ void zero_acc_kernel() {
    if (threadIdx.x < 4) g_acc[threadIdx.x] = 0.0;
}

__global__ void final_kernel(float* __restrict__ out) {
    double clrecall = (g_acc[0] + 1e-12) / (g_acc[1] + 1e-12);
    double clacc    = (g_acc[2] + 1e-12) / (g_acc[3] + 1e-12);
    double cldice   = 2.0 * clrecall * clacc / (clrecall + clacc);
    out[0] = (float)(1.0 - cldice);
}

extern "C" void kernel_launch(void* const* d_in, const int* in_sizes, int n_in,
                              void* d_out, int out_size) {
    const float* pred   = (const float*)d_in[0];
    const float* target = (const float*)d_in[1];
    float* out = (float*)d_out;

    dim3 blk(16, 16, 1);
    dim3 grd(NB, NB, 4 * NCH);

    zero_acc_kernel<<<1, 32>>>();
    fused_iter<0><<<grd, blk>>>(0, 0, pred, target);   // inputs -> buf0
    fused_iter<1><<<grd, blk>>>(0, 1, pred, target);   // buf0 -> buf1
    fused_iter<1><<<grd, blk>>>(1, 0, pred, target);   // buf1 -> buf0
    fused_iter<1><<<grd, blk>>>(0, 1, pred, target);   // buf0 -> buf1
    fused_iter<2><<<grd, blk>>>(1, 0, pred, target);   // buf1 -> sums
    final_kernel<<<1, 1>>>(out);
}